// round 2
// baseline (speedup 1.0000x reference)
#include <cuda_runtime.h>

// Problem constants
#define B_TOK 32768
#define DIM   256
#define E_NUM 8

// ---------------------------------------------------------------------------
// Routing scratch (device globals — no allocations allowed)
// ---------------------------------------------------------------------------
__device__ int   g_cnt[E_NUM];
__device__ int   g_ridx[E_NUM * B_TOK];
__device__ float g_rwt [E_NUM * B_TOK];

__global__ void zero_cnt_kernel() {
    if (threadIdx.x < E_NUM) g_cnt[threadIdx.x] = 0;
}

// ---------------------------------------------------------------------------
// Register-blocked 64x256 @ 256x256 fp32 GEMM tile.
// Block: 256 threads. warp id tc = token group (8 tokens), lane jc = col group
// (8 cols). Each thread accumulates an 8x8 sub-tile in registers.
// In: smem [64][256]. W: global (row-major [256][256]). Wt: smem staging
// [32][256]. Ends with __syncthreads() so the caller may overwrite In.
// ---------------------------------------------------------------------------
__device__ __forceinline__ void gemm_64x256(
    const float* __restrict__ In, const float4* __restrict__ W4g,
    float* __restrict__ Wt, float (&acc)[8][8], int tc, int jc, int tid)
{
    float4* Wt4 = (float4*)Wt;
#pragma unroll
    for (int a = 0; a < 8; a++)
#pragma unroll
        for (int b = 0; b < 8; b++) acc[a][b] = 0.f;

    for (int dt = 0; dt < 256; dt += 32) {
        __syncthreads();
#pragma unroll
        for (int i = 0; i < 8; i++)
            Wt4[tid + i * 256] = W4g[dt * 64 + tid + i * 256];
        __syncthreads();
#pragma unroll 1
        for (int dd = 0; dd < 32; dd += 4) {
            float4 xq[8];
#pragma unroll
            for (int tt = 0; tt < 8; tt++)
                xq[tt] = *(const float4*)&In[(tc * 8 + tt) * 256 + dt + dd];
#pragma unroll
            for (int q = 0; q < 4; q++) {
                float4 wa = Wt4[(dd + q) * 64 + jc * 2];
                float4 wb = Wt4[(dd + q) * 64 + jc * 2 + 1];
                float wv[8] = {wa.x, wa.y, wa.z, wa.w, wb.x, wb.y, wb.z, wb.w};
#pragma unroll
                for (int tt = 0; tt < 8; tt++) {
                    float xv = ((const float*)&xq[tt])[q];
#pragma unroll
                    for (int cc = 0; cc < 8; cc++)
                        acc[tt][cc] = fmaf(xv, wv[cc], acc[tt][cc]);
                }
            }
        }
    }
    __syncthreads();
}

// bias + LayerNorm + ReLU on the register tile, store to smem Out.
// Token rows are warp-private -> LN reduction is pure warp shuffles.
// bias/gma/bta pre-offset to expert (256 floats each).
__device__ __forceinline__ void bias_ln_relu_store(
    float (&acc)[8][8], const float* __restrict__ bias,
    const float* __restrict__ gma, const float* __restrict__ bta,
    float* __restrict__ Out, int tc, int jc)
{
    float bj[8], gj[8], ej[8];
#pragma unroll
    for (int cc = 0; cc < 8; cc++) {
        bj[cc] = bias[jc * 8 + cc];
        gj[cc] = gma[jc * 8 + cc];
        ej[cc] = bta[jc * 8 + cc];
    }
#pragma unroll
    for (int tt = 0; tt < 8; tt++) {
        float s = 0.f, s2 = 0.f;
#pragma unroll
        for (int cc = 0; cc < 8; cc++) {
            float v = acc[tt][cc] + bj[cc];
            acc[tt][cc] = v;
            s += v;
            s2 = fmaf(v, v, s2);
        }
#pragma unroll
        for (int o = 16; o > 0; o >>= 1) {
            s  += __shfl_xor_sync(0xffffffffu, s, o);
            s2 += __shfl_xor_sync(0xffffffffu, s2, o);
        }
        float m    = s * (1.f / 256.f);
        float var  = s2 * (1.f / 256.f) - m * m;
        float rstd = rsqrtf(var + 1e-5f);
        float ov[8];
#pragma unroll
        for (int cc = 0; cc < 8; cc++) {
            float v = (acc[tt][cc] - m) * rstd * gj[cc] + ej[cc];
            ov[cc] = fmaxf(v, 0.f);
        }
        float4* O4 = (float4*)&Out[(tc * 8 + tt) * 256 + jc * 8];
        O4[0] = make_float4(ov[0], ov[1], ov[2], ov[3]);
        O4[1] = make_float4(ov[4], ov[5], ov[6], ov[7]);
    }
}

// ---------------------------------------------------------------------------
// Gating: h = relu(x@gw1+gb1); logits = h@gw2+gb2; top-2 of softmax
// (renormalized -> softmax denominator cancels); routed list build.
// Block = 64 tokens, 256 threads. Dyn smem: A[64*256] + Wt[32*256].
// ---------------------------------------------------------------------------
#define GATE_SMEM ((64 * 256 + 32 * 256) * 4)

__global__ __launch_bounds__(256, 2) void gating_kernel(
    const float* __restrict__ x,
    const float* __restrict__ gw1, const float* __restrict__ gb1,
    const float* __restrict__ gw2, const float* __restrict__ gb2)
{
    extern __shared__ float sm[];
    float* A  = sm;              // 64 x 256
    float* Wt = sm + 64 * 256;   // 32 x 256
    __shared__ float lgs[64 * 8];
    __shared__ int scnt[E_NUM], sbase[E_NUM], soff[E_NUM];

    int tid = threadIdx.x;
    int tc = tid >> 5;
    int jc = tid & 31;

    // load x tile (contiguous rows)
    const float4* x4 = (const float4*)(x + (size_t)blockIdx.x * 64 * 256);
    float4* A4 = (float4*)A;
#pragma unroll
    for (int i = 0; i < 16; i++) A4[tid + i * 256] = x4[tid + i * 256];

    float acc[8][8];
    gemm_64x256(A, (const float4*)gw1, Wt, acc, tc, jc, tid);

    // bias + relu, write h back into A (gemm ended with syncthreads)
    {
        float bj[8];
#pragma unroll
        for (int cc = 0; cc < 8; cc++) bj[cc] = gb1[jc * 8 + cc];
#pragma unroll
        for (int tt = 0; tt < 8; tt++) {
            float ov[8];
#pragma unroll
            for (int cc = 0; cc < 8; cc++)
                ov[cc] = fmaxf(acc[tt][cc] + bj[cc], 0.f);
            float4* O4 = (float4*)&A[(tc * 8 + tt) * 256 + jc * 8];
            O4[0] = make_float4(ov[0], ov[1], ov[2], ov[3]);
            O4[1] = make_float4(ov[4], ov[5], ov[6], ov[7]);
        }
    }
    if (tid < E_NUM) { scnt[tid] = 0; soff[tid] = 0; }
    __syncthreads();

    // layer 2: 64 tokens x 8 experts = 512 outputs
    for (int idx = tid; idx < 512; idx += 256) {
        int t = idx >> 3, e = idx & 7;
        float s = gb2[e];
        for (int k = 0; k < 256; k++)
            s = fmaf(A[t * 256 + k], gw2[k * 8 + e], s);
        lgs[t * 8 + e] = s;
    }
    __syncthreads();

    // top-2 + block-aggregated routing
    int i0 = 0, i1 = 0;
    float w0f = 0.f, w1f = 0.f;
    int token = blockIdx.x * 64 + tid;
    if (tid < 64) {
        float l0 = -1e30f, l1 = -1e30f;
#pragma unroll
        for (int e = 0; e < E_NUM; e++) {
            float l = lgs[tid * 8 + e];
            if (l > l0) { l1 = l0; i1 = i0; l0 = l; i0 = e; }
            else if (l > l1) { l1 = l; i1 = e; }
        }
        float r = expf(l1 - l0);
        w0f = 1.f / (1.f + r);
        w1f = r * w0f;
        atomicAdd(&scnt[i0], 1);
        atomicAdd(&scnt[i1], 1);
    }
    __syncthreads();
    if (tid < E_NUM) sbase[tid] = atomicAdd(&g_cnt[tid], scnt[tid]);
    __syncthreads();
    if (tid < 64) {
        int p0 = atomicAdd(&soff[i0], 1);
        int gpos0 = sbase[i0] + p0;
        g_ridx[i0 * B_TOK + gpos0] = token;
        g_rwt [i0 * B_TOK + gpos0] = w0f;
        int p1 = atomicAdd(&soff[i1], 1);
        int gpos1 = sbase[i1] + p1;
        g_ridx[i1 * B_TOK + gpos1] = token;
        g_rwt [i1 * B_TOK + gpos1] = w1f;
    }
}

// ---------------------------------------------------------------------------
// Expert compute over routed tokens. Grid (512, E). Early-exit beyond count.
// Dyn smem: A[64*256] + Bf[64*256] + Wt[32*256] = 160 KB.
// ---------------------------------------------------------------------------
#define EXP_SMEM ((64 * 256 * 2 + 32 * 256) * 4)

__global__ __launch_bounds__(256) void expert_kernel(
    const float* __restrict__ x,
    const float* __restrict__ w1, const float* __restrict__ b1,
    const float* __restrict__ g1, const float* __restrict__ be1,
    const float* __restrict__ w2, const float* __restrict__ b2,
    const float* __restrict__ g2, const float* __restrict__ be2,
    const float* __restrict__ w3, const float* __restrict__ b3,
    float* __restrict__ out)
{
    int e = blockIdx.y;
    int n = g_cnt[e];
    int start = blockIdx.x * 64;
    if (start >= n) return;

    extern __shared__ float sm[];
    float* A  = sm;                  // ping
    float* Bf = sm + 64 * 256;       // pong
    float* Wt = sm + 2 * 64 * 256;   // weight staging
    __shared__ int   stok[64];
    __shared__ float sgw[64];

    int tid = threadIdx.x;
    int tc = tid >> 5;
    int jc = tid & 31;

    if (tid < 64) {
        int r = start + tid;
        if (r < n) {
            stok[tid] = g_ridx[e * B_TOK + r];
            sgw [tid] = g_rwt [e * B_TOK + r];
        } else {
            stok[tid] = -1;
            sgw [tid] = 0.f;
        }
    }
    __syncthreads();

    // gather x rows into A (float4, coalesced within rows)
    const float4* x4 = (const float4*)x;
    float4* A4 = (float4*)A;
#pragma unroll
    for (int i = 0; i < 16; i++) {
        int idx = tid + i * 256;
        int row = idx >> 6, c = idx & 63;
        int tok = stok[row];
        A4[idx] = (tok >= 0) ? x4[(size_t)tok * 64 + c]
                             : make_float4(0.f, 0.f, 0.f, 0.f);
    }

    const size_t we = (size_t)e * 256 * 256;
    float acc[8][8];

    // layer 1: A -> Bf
    gemm_64x256(A, (const float4*)(w1 + we), Wt, acc, tc, jc, tid);
    bias_ln_relu_store(acc, b1 + e * 256, g1 + e * 256, be1 + e * 256, Bf, tc, jc);

    // layer 2: Bf -> A (x no longer needed)
    gemm_64x256(Bf, (const float4*)(w2 + we), Wt, acc, tc, jc, tid);
    bias_ln_relu_store(acc, b2 + e * 256, g2 + e * 256, be2 + e * 256, A, tc, jc);

    // layer 3: A -> gated atomic accumulate into out
    gemm_64x256(A, (const float4*)(w3 + we), Wt, acc, tc, jc, tid);
    {
        float bj[8];
#pragma unroll
        for (int cc = 0; cc < 8; cc++) bj[cc] = b3[e * 256 + jc * 8 + cc];
#pragma unroll
        for (int tt = 0; tt < 8; tt++) {
            int row = tc * 8 + tt;
            int tok = stok[row];
            if (tok < 0) continue;
            float w = sgw[row];
            float* dst = out + (size_t)tok * 256 + jc * 8;
#pragma unroll
            for (int cc = 0; cc < 8; cc++)
                atomicAdd(dst + cc, (acc[tt][cc] + bj[cc]) * w);
        }
    }
}

// ---------------------------------------------------------------------------
// Launch
// ---------------------------------------------------------------------------
extern "C" void kernel_launch(void* const* d_in, const int* in_sizes, int n_in,
                              void* d_out, int out_size)
{
    (void)in_sizes; (void)n_in;
    const float* x   = (const float*)d_in[0];
    const float* gw1 = (const float*)d_in[1];
    const float* gb1 = (const float*)d_in[2];
    const float* gw2 = (const float*)d_in[3];
    const float* gb2 = (const float*)d_in[4];
    const float* w1  = (const float*)d_in[5];
    const float* b1  = (const float*)d_in[6];
    const float* g1  = (const float*)d_in[7];
    const float* be1 = (const float*)d_in[8];
    const float* w2  = (const float*)d_in[9];
    const float* b2  = (const float*)d_in[10];
    const float* g2  = (const float*)d_in[11];
    const float* be2 = (const float*)d_in[12];
    const float* w3  = (const float*)d_in[13];
    const float* b3  = (const float*)d_in[14];
    float* out = (float*)d_out;

    cudaFuncSetAttribute(gating_kernel,
        cudaFuncAttributeMaxDynamicSharedMemorySize, GATE_SMEM);
    cudaFuncSetAttribute(expert_kernel,
        cudaFuncAttributeMaxDynamicSharedMemorySize, EXP_SMEM);

    zero_cnt_kernel<<<1, 32>>>();
    cudaMemsetAsync(d_out, 0, (size_t)out_size * sizeof(float));
    gating_kernel<<<B_TOK / 64, 256, GATE_SMEM>>>(x, gw1, gb1, gw2, gb2);
    expert_kernel<<<dim3(B_TOK / 64, E_NUM), 256, EXP_SMEM>>>(
        x, w1, b1, g1, be1, w2, b2, g2, be2, w3, b3, out);
}

// round 4
// speedup vs baseline: 2.7045x; 2.7045x over previous
#include <cuda_runtime.h>
#include <cuda_fp16.h>
#include <cstdint>

#define B_TOK 32768
#define E_NUM 8

// ---------------------------------------------------------------------------
// Device globals
// ---------------------------------------------------------------------------
__device__ int   g_cnt[E_NUM];
__device__ int   g_ridx[E_NUM * B_TOK];   // token | (k<<15)
__device__ float g_rwt [E_NUM * B_TOK];
__device__ __half g_xhi[B_TOK * 256];
__device__ __half g_xlo[B_TOK * 256];
// 25 slots: 0..23 = layer*8+expert, 24 = gating gw1. Tiled fragment layout:
// per slot: [k16(16)][n8(32)] frags of 256B (2 8x8 matrices: k0-7, k8-15 rows=n)
__device__ __half g_wthi[25 * 65536];
__device__ __half g_wtlo[25 * 65536];
__device__ float g_scr[2 * B_TOK * 256];

__global__ void zero_cnt_kernel() {
    if (threadIdx.x < E_NUM) g_cnt[threadIdx.x] = 0;
}

// ---------------------------------------------------------------------------
// Helpers
// ---------------------------------------------------------------------------
__device__ __forceinline__ uint32_t smem_u32(const void* p) {
    uint32_t a;
    asm("{ .reg .u64 t; cvta.to.shared.u64 t, %1; cvt.u32.u64 %0, t; }" : "=r"(a) : "l"(p));
    return a;
}
__device__ __forceinline__ void cp_async16(uint32_t dst, const void* src) {
    asm volatile("cp.async.cg.shared.global [%0], [%1], 16;" :: "r"(dst), "l"(src));
}
__device__ __forceinline__ void cp_async16z(uint32_t dst, const void* src, int srcsz) {
    asm volatile("cp.async.cg.shared.global [%0], [%1], 16, %2;"
                 :: "r"(dst), "l"(src), "r"(srcsz));
}
#define CP_COMMIT() asm volatile("cp.async.commit_group;" ::: "memory")
#define CP_WAIT1()  asm volatile("cp.async.wait_group 1;" ::: "memory")
#define CP_WAIT0()  asm volatile("cp.async.wait_group 0;" ::: "memory")

__device__ __forceinline__ void ldsm4(uint32_t* r, uint32_t addr) {
    asm volatile("ldmatrix.sync.aligned.m8n8.x4.shared.b16 {%0,%1,%2,%3}, [%4];"
                 : "=r"(r[0]), "=r"(r[1]), "=r"(r[2]), "=r"(r[3]) : "r"(addr));
}
__device__ __forceinline__ void mma16816(float* c, const uint32_t* a, const uint32_t* b) {
    asm volatile("mma.sync.aligned.m16n8k16.row.col.f32.f16.f16.f32 "
                 "{%0,%1,%2,%3}, {%4,%5,%6,%7}, {%8,%9}, {%0,%1,%2,%3};"
                 : "+f"(c[0]), "+f"(c[1]), "+f"(c[2]), "+f"(c[3])
                 : "r"(a[0]), "r"(a[1]), "r"(a[2]), "r"(a[3]), "r"(b[0]), "r"(b[1]));
}
__device__ __forceinline__ uint32_t packh2(float a, float b) {
    __half2 h = __floats2half2_rn(a, b);
    return *(uint32_t*)&h;
}
__device__ __forceinline__ uint32_t packh2_res(float a, float b, uint32_t hi) {
    __half2 h = *(__half2*)&hi;
    float2 f = __half22float2(h);
    return packh2(a - f.x, b - f.y);
}

// ---------------------------------------------------------------------------
// Shared memory layout (dynamic)
//   A frags:  [var(2)][k16(16)][m16(8)] * 512B          = 131072
//   W dbuf:   2 bufs * ([var][k16in(2)][n8(32)] * 256B) = 65536
// ---------------------------------------------------------------------------
#define A_VAR_STRIDE 65536
#define W_OFF  131072
#define WBUF_BYTES 32768
// expert extras
#define STAT_OFF 196608
#define SBV_OFF  198656
#define SGV_OFF  199680
#define SEV_OFF  200704
#define SIDX_OFF 201728
#define SGW_OFF  202240
#define EXP_SMEM 203776
// gating extras
#define GT_GW2  196608
#define GT_GB1  204800
#define GT_LGS  205888
#define GT_GB2  209984
#define GT_SCNT 210048
#define GT_SBASE 210080
#define GT_SOFF 210112
#define GATE_SMEM 212992

// A fragment byte offset for element (row m, k) pair-base (k even within 16B ok)
__device__ __forceinline__ uint32_t a_frag_off(int m, int k) {
    return (uint32_t)((((k >> 4) * 8 + (m >> 4)) * 512) +
                      ((((k >> 3) & 1) * 2 + ((m >> 3) & 1)) * 128) +
                      ((m & 7) * 16) + ((k & 7) * 2));
}

// copy one 32KB W chunk (hi 16KB + lo 16KB) into a smem buffer
__device__ __forceinline__ void copy_wchunk(uint32_t dst, const __half* wth,
                                            const __half* wtl, int c, int tid) {
    const char* sh = (const char*)wth + c * 16384;
    const char* sl = (const char*)wtl + c * 16384;
#pragma unroll
    for (int u = 0; u < 4; u++) {
        int o = (tid + u * 256) * 16;
        cp_async16(dst + o, sh + o);
    }
#pragma unroll
    for (int u = 0; u < 4; u++) {
        int o = (tid + u * 256) * 16;
        cp_async16(dst + 16384 + o, sl + o);
    }
}

// ---------------------------------------------------------------------------
// Shared mainloop: 128x256 fp32 = split-fp16 A (smem frags) @ W^T (tiled global)
// acc[mf][nf][4]; warp (wm 0..3, wn 0..1) tile 32 rows x 128 cols.
// ---------------------------------------------------------------------------
__device__ __forceinline__ void mma_mainloop(
    uint32_t sa, const __half* wth, const __half* wtl,
    float (&acc)[2][16][4], int wm, int wn, int lane, int tid)
{
#pragma unroll
    for (int a = 0; a < 2; a++)
#pragma unroll
        for (int b = 0; b < 16; b++)
#pragma unroll
            for (int c = 0; c < 4; c++) acc[a][b][c] = 0.f;

    uint32_t aW = sa + W_OFF;
    copy_wchunk(aW, wth, wtl, 0, tid);
    CP_COMMIT();

#pragma unroll 1
    for (int c = 0; c < 8; c++) {
        if (c < 7) {
            copy_wchunk(aW + ((c + 1) & 1) * WBUF_BYTES, wth, wtl, c + 1, tid);
            CP_COMMIT();
            CP_WAIT1();
        } else {
            CP_WAIT0();
        }
        __syncthreads();
        uint32_t wb = aW + (c & 1) * WBUF_BYTES;
#pragma unroll
        for (int ks = 0; ks < 2; ks++) {
            int k16 = c * 2 + ks;
            uint32_t ah[2][4], al[2][4];
#pragma unroll
            for (int mf = 0; mf < 2; mf++) {
                uint32_t base = sa + (uint32_t)((k16 * 8 + wm * 2 + mf) * 512) + lane * 16;
                ldsm4(ah[mf], base);
                ldsm4(al[mf], base + A_VAR_STRIDE);
            }
#pragma unroll
            for (int j = 0; j < 8; j++) {
                uint32_t b[4];
                uint32_t wbase = wb + (uint32_t)((ks * 32 + wn * 16 + j * 2) * 256) + lane * 16;
                ldsm4(b, wbase);  // Whi pair
#pragma unroll
                for (int mf = 0; mf < 2; mf++) {
                    mma16816(acc[mf][j * 2],     ah[mf], b);
                    mma16816(acc[mf][j * 2 + 1], ah[mf], b + 2);
                    mma16816(acc[mf][j * 2],     al[mf], b);
                    mma16816(acc[mf][j * 2 + 1], al[mf], b + 2);
                }
                ldsm4(b, wbase + 16384);  // Wlo pair
#pragma unroll
                for (int mf = 0; mf < 2; mf++) {
                    mma16816(acc[mf][j * 2],     ah[mf], b);
                    mma16816(acc[mf][j * 2 + 1], ah[mf], b + 2);
                }
            }
        }
        __syncthreads();
    }
}

// ---------------------------------------------------------------------------
// Prep kernels
// ---------------------------------------------------------------------------
__global__ void prep_x_kernel(const float* __restrict__ x) {
    int i = blockIdx.x * 256 + threadIdx.x;
    float4 v = ((const float4*)x)[i];
    __half h0 = __float2half_rn(v.x), h1 = __float2half_rn(v.y);
    __half h2 = __float2half_rn(v.z), h3 = __float2half_rn(v.w);
    uint2 hp, lp;
    hp.x = (uint32_t)__half_as_ushort(h0) | ((uint32_t)__half_as_ushort(h1) << 16);
    hp.y = (uint32_t)__half_as_ushort(h2) | ((uint32_t)__half_as_ushort(h3) << 16);
    __half l0 = __float2half_rn(v.x - __half2float(h0));
    __half l1 = __float2half_rn(v.y - __half2float(h1));
    __half l2 = __float2half_rn(v.z - __half2float(h2));
    __half l3 = __float2half_rn(v.w - __half2float(h3));
    lp.x = (uint32_t)__half_as_ushort(l0) | ((uint32_t)__half_as_ushort(l1) << 16);
    lp.y = (uint32_t)__half_as_ushort(l2) | ((uint32_t)__half_as_ushort(l3) << 16);
    ((uint2*)g_xhi)[i] = hp;
    ((uint2*)g_xlo)[i] = lp;
}

// One block per (k16, slot): read 16x256 fp32, emit tiled fp16 hi/lo frags.
__global__ void prep_w_kernel(const float* __restrict__ w1, const float* __restrict__ w2,
                              const float* __restrict__ w3, const float* __restrict__ gw1) {
    __shared__ float sm[16 * 256];
    int k16 = blockIdx.x, slot = blockIdx.y;
    const float* src;
    if (slot < 24) {
        int l = slot >> 3, e = slot & 7;
        src = ((l == 0) ? w1 : (l == 1) ? w2 : w3) + (size_t)e * 65536;
    } else {
        src = gw1;
    }
    src += (size_t)k16 * 16 * 256;
    int tid = threadIdx.x;
#pragma unroll
    for (int u = 0; u < 4; u++)
        ((float4*)sm)[tid + u * 256] = ((const float4*)src)[tid + u * 256];
    __syncthreads();

#pragma unroll
    for (int u = 0; u < 4; u++) {
        int id = tid + u * 256;           // 0..1023
        int var = id >> 9;
        int rem = id & 511;
        int n8 = rem >> 4, sub = rem & 15;
        int kpart = sub >> 3, nrow = sub & 7;
        int n = n8 * 8 + nrow;
        ushort h[8];
#pragma unroll
        for (int i = 0; i < 8; i++) {
            float v = sm[(kpart * 8 + i) * 256 + n];
            __half hi = __float2half_rn(v);
            if (var == 0) h[i] = __half_as_ushort(hi);
            else          h[i] = __half_as_ushort(__float2half_rn(v - __half2float(hi)));
        }
        __half* dstbase = (var == 0) ? g_wthi : g_wtlo;
        uint4* dst = (uint4*)(dstbase + (size_t)slot * 65536 +
                              (k16 * 32 + n8) * 128 + kpart * 64 + nrow * 8);
        uint4 pk;
        pk.x = (uint32_t)h[0] | ((uint32_t)h[1] << 16);
        pk.y = (uint32_t)h[2] | ((uint32_t)h[3] << 16);
        pk.z = (uint32_t)h[4] | ((uint32_t)h[5] << 16);
        pk.w = (uint32_t)h[6] | ((uint32_t)h[7] << 16);
        *dst = pk;
    }
}

// ---------------------------------------------------------------------------
// Gating kernel: 128 tokens/CTA, mma layer1 + fp32 layer2 + top-2 routing
// ---------------------------------------------------------------------------
__global__ __launch_bounds__(256, 1) void gating_kernel(
    const float* __restrict__ gb1,
    const float* __restrict__ gw2, const float* __restrict__ gb2)
{
    extern __shared__ char smraw[];
    uint32_t sa = smem_u32(smraw);
    float* hsm  = (float*)smraw;                    // after GEMM: h fp32 [128][260]
    float* gw2s = (float*)(smraw + GT_GW2);
    float* gb1s = (float*)(smraw + GT_GB1);
    float* lgs  = (float*)(smraw + GT_LGS);
    float* gb2s = (float*)(smraw + GT_GB2);
    int* scnt  = (int*)(smraw + GT_SCNT);
    int* sbase = (int*)(smraw + GT_SBASE);
    int* soff  = (int*)(smraw + GT_SOFF);

    int tid = threadIdx.x;
    int lane = tid & 31, warp = tid >> 5;
    int wm = warp & 3, wn = warp >> 2;

    // stage gw2 / gb1 / gb2, init counters
#pragma unroll
    for (int u = 0; u < 8; u++) gw2s[tid + u * 256] = gw2[tid + u * 256];
    gb1s[tid] = gb1[tid];
    if (tid < 8) { gb2s[tid] = gb2[tid]; scnt[tid] = 0; soff[tid] = 0; }

    // gather x tile into A frags (cp.async)
    int rowbase = blockIdx.x * 128;
#pragma unroll
    for (int u = 0; u < 32; u++) {
        int id = tid + u * 256;             // 0..8191
        int var = id >> 12;
        int rem = id & 4095;
        int row = rem >> 5, k8 = rem & 31;
        const __half* src = ((var == 0) ? g_xhi : g_xlo) +
                            (size_t)(rowbase + row) * 256 + k8 * 8;
        uint32_t dst = sa + var * A_VAR_STRIDE + a_frag_off(row, k8 * 8);
        cp_async16(dst, src);
    }
    CP_COMMIT();

    float acc[2][16][4];
    mma_mainloop(sa, g_wthi + 24 * 65536, g_wtlo + 24 * 65536, acc, wm, wn, lane, tid);

    // epilogue: h = relu(acc + gb1) -> hsm fp32 pitch 260
    int q = lane & 3, lr = lane >> 2;
#pragma unroll
    for (int mf = 0; mf < 2; mf++)
#pragma unroll
        for (int h = 0; h < 2; h++) {
            int row = wm * 32 + mf * 16 + h * 8 + lr;
#pragma unroll
            for (int nf = 0; nf < 16; nf++) {
                int col = wn * 128 + nf * 8 + q * 2;
                float2 o;
                o.x = fmaxf(acc[mf][nf][2 * h]     + gb1s[col],     0.f);
                o.y = fmaxf(acc[mf][nf][2 * h + 1] + gb1s[col + 1], 0.f);
                *(float2*)(hsm + row * 260 + col) = o;
            }
        }
    __syncthreads();

    // layer 2: logits[128][8]
    {
        int t = tid >> 1, eb = (tid & 1) * 4;
        const float* hr = hsm + t * 260;
        float s0 = gb2s[eb], s1 = gb2s[eb + 1], s2 = gb2s[eb + 2], s3 = gb2s[eb + 3];
#pragma unroll 4
        for (int k = 0; k < 256; k++) {
            float hv = hr[k];
            const float* g = gw2s + k * 8 + eb;
            s0 = fmaf(hv, g[0], s0);
            s1 = fmaf(hv, g[1], s1);
            s2 = fmaf(hv, g[2], s2);
            s3 = fmaf(hv, g[3], s3);
        }
        float* lp = lgs + t * 8 + eb;
        lp[0] = s0; lp[1] = s1; lp[2] = s2; lp[3] = s3;
    }
    __syncthreads();

    // top-2 + routing
    int i0 = 0, i1 = 0;
    float w0f = 0.f, w1f = 0.f;
    int token = rowbase + tid;
    if (tid < 128) {
        float l0 = -1e30f, l1 = -1e30f;
#pragma unroll
        for (int e = 0; e < E_NUM; e++) {
            float l = lgs[tid * 8 + e];
            if (l > l0) { l1 = l0; i1 = i0; l0 = l; i0 = e; }
            else if (l > l1) { l1 = l; i1 = e; }
        }
        float r = expf(l1 - l0);
        w0f = 1.f / (1.f + r);
        w1f = r * w0f;
        atomicAdd(&scnt[i0], 1);
        atomicAdd(&scnt[i1], 1);
    }
    __syncthreads();
    if (tid < E_NUM) sbase[tid] = atomicAdd(&g_cnt[tid], scnt[tid]);
    __syncthreads();
    if (tid < 128) {
        int p0 = atomicAdd(&soff[i0], 1);
        g_ridx[i0 * B_TOK + sbase[i0] + p0] = token;
        g_rwt [i0 * B_TOK + sbase[i0] + p0] = w0f;
        int p1 = atomicAdd(&soff[i1], 1);
        g_ridx[i1 * B_TOK + sbase[i1] + p1] = token | 32768;
        g_rwt [i1 * B_TOK + sbase[i1] + p1] = w1f;
    }
}

// ---------------------------------------------------------------------------
// Expert kernel
// ---------------------------------------------------------------------------
__global__ __launch_bounds__(256, 1) void expert_kernel(
    const float* __restrict__ b1, const float* __restrict__ g1, const float* __restrict__ be1,
    const float* __restrict__ b2, const float* __restrict__ g2, const float* __restrict__ be2,
    const float* __restrict__ b3)
{
    int e = blockIdx.y;
    int n = g_cnt[e];
    int start = blockIdx.x * 128;
    if (start >= n) return;

    extern __shared__ char smraw[];
    uint32_t sa = smem_u32(smraw);
    float* sstat = (float*)(smraw + STAT_OFF);
    float* sbv = (float*)(smraw + SBV_OFF);
    float* sgv = (float*)(smraw + SGV_OFF);
    float* sev = (float*)(smraw + SEV_OFF);
    int*   sidx = (int*)(smraw + SIDX_OFF);
    float* sgwv = (float*)(smraw + SGW_OFF);

    int tid = threadIdx.x;
    int lane = tid & 31, warp = tid >> 5;
    int wm = warp & 3, wn = warp >> 2;

    if (tid < 128) {
        int r = start + tid;
        if (r < n) { sidx[tid] = g_ridx[e * B_TOK + r]; sgwv[tid] = g_rwt[e * B_TOK + r]; }
        else       { sidx[tid] = -1; sgwv[tid] = 0.f; }
    }
    __syncthreads();

    // gather routed x rows (hi/lo) into A frags
#pragma unroll
    for (int u = 0; u < 32; u++) {
        int id = tid + u * 256;
        int var = id >> 12;
        int rem = id & 4095;
        int row = rem >> 5, k8 = rem & 31;
        int idx = sidx[row];
        int tok = idx & 32767;
        const __half* src = ((var == 0) ? g_xhi : g_xlo) + (size_t)tok * 256 + k8 * 8;
        uint32_t dst = sa + var * A_VAR_STRIDE + a_frag_off(row, k8 * 8);
        cp_async16z(dst, src, (idx >= 0) ? 16 : 0);
    }
    CP_COMMIT();

    const float* Bp[3] = {b1 + e * 256, b2 + e * 256, b3 + e * 256};
    const float* Gp[2] = {g1 + e * 256, g2 + e * 256};
    const float* Ep[2] = {be1 + e * 256, be2 + e * 256};

    float acc[2][16][4];
    int q = lane & 3, lr = lane >> 2;

#pragma unroll 1
    for (int layer = 0; layer < 3; layer++) {
        sbv[tid] = Bp[layer][tid];
        if (layer < 2) { sgv[tid] = Gp[layer][tid]; sev[tid] = Ep[layer][tid]; }
        int slot = layer * 8 + e;
        mma_mainloop(sa, g_wthi + (size_t)slot * 65536, g_wtlo + (size_t)slot * 65536,
                     acc, wm, wn, lane, tid);

        if (layer < 2) {
            // bias + partial stats
#pragma unroll
            for (int mf = 0; mf < 2; mf++)
#pragma unroll
                for (int h = 0; h < 2; h++) {
                    int row = wm * 32 + mf * 16 + h * 8 + lr;
                    float s = 0.f, s2 = 0.f;
#pragma unroll
                    for (int nf = 0; nf < 16; nf++) {
                        int col = wn * 128 + nf * 8 + q * 2;
                        float v0 = acc[mf][nf][2 * h]     + sbv[col];
                        float v1 = acc[mf][nf][2 * h + 1] + sbv[col + 1];
                        acc[mf][nf][2 * h] = v0;
                        acc[mf][nf][2 * h + 1] = v1;
                        s += v0 + v1;
                        s2 = fmaf(v0, v0, fmaf(v1, v1, s2));
                    }
                    s  += __shfl_xor_sync(0xffffffffu, s, 1);
                    s2 += __shfl_xor_sync(0xffffffffu, s2, 1);
                    s  += __shfl_xor_sync(0xffffffffu, s, 2);
                    s2 += __shfl_xor_sync(0xffffffffu, s2, 2);
                    if (q == 0) {
                        sstat[(row * 2 + wn) * 2]     = s;
                        sstat[(row * 2 + wn) * 2 + 1] = s2;
                    }
                }
            __syncthreads();
            // normalize + relu + re-split into A frags
#pragma unroll
            for (int mf = 0; mf < 2; mf++)
#pragma unroll
                for (int h = 0; h < 2; h++) {
                    int row = wm * 32 + mf * 16 + h * 8 + lr;
                    float s  = sstat[row * 4]     + sstat[row * 4 + 2];
                    float s2 = sstat[row * 4 + 1] + sstat[row * 4 + 3];
                    float m = s * (1.f / 256.f);
                    float rstd = rsqrtf(s2 * (1.f / 256.f) - m * m + 1e-5f);
#pragma unroll
                    for (int nf = 0; nf < 16; nf++) {
                        int col = wn * 128 + nf * 8 + q * 2;
                        float v0 = fmaxf((acc[mf][nf][2 * h] - m) * rstd * sgv[col] + sev[col], 0.f);
                        float v1 = fmaxf((acc[mf][nf][2 * h + 1] - m) * rstd * sgv[col + 1] + sev[col + 1], 0.f);
                        uint32_t hi = packh2(v0, v1);
                        uint32_t lo = packh2_res(v0, v1, hi);
                        uint32_t dst = sa + a_frag_off(row, col);
                        asm volatile("st.shared.b32 [%0], %1;" :: "r"(dst), "r"(hi));
                        asm volatile("st.shared.b32 [%0+65536], %1;" :: "r"(dst), "r"(lo));
                    }
                }
            __syncthreads();
        } else {
            // output epilogue: (acc + b3) * gate -> scratch slot
#pragma unroll
            for (int mf = 0; mf < 2; mf++)
#pragma unroll
                for (int h = 0; h < 2; h++) {
                    int row = wm * 32 + mf * 16 + h * 8 + lr;
                    int idx = sidx[row];
                    if (idx < 0) continue;
                    float g = sgwv[row];
                    float* dst = g_scr + (size_t)(idx >> 15) * B_TOK * 256 +
                                 (size_t)(idx & 32767) * 256;
#pragma unroll
                    for (int nf = 0; nf < 16; nf++) {
                        int col = wn * 128 + nf * 8 + q * 2;
                        float2 o;
                        o.x = (acc[mf][nf][2 * h]     + sbv[col])     * g;
                        o.y = (acc[mf][nf][2 * h + 1] + sbv[col + 1]) * g;
                        *(float2*)(dst + col) = o;
                    }
                }
        }
    }
}

// ---------------------------------------------------------------------------
// Combine the two top-k slots
// ---------------------------------------------------------------------------
__global__ void combine_kernel(float* __restrict__ out) {
    int i = blockIdx.x * 256 + threadIdx.x;
    float4 a = ((const float4*)g_scr)[i];
    float4 b = ((const float4*)(g_scr + (size_t)B_TOK * 256))[i];
    float4 o;
    o.x = a.x + b.x; o.y = a.y + b.y; o.z = a.z + b.z; o.w = a.w + b.w;
    ((float4*)out)[i] = o;
}

// ---------------------------------------------------------------------------
// Launch
// ---------------------------------------------------------------------------
extern "C" void kernel_launch(void* const* d_in, const int* in_sizes, int n_in,
                              void* d_out, int out_size)
{
    (void)in_sizes; (void)n_in; (void)out_size;
    const float* x   = (const float*)d_in[0];
    const float* gw1 = (const float*)d_in[1];
    const float* gb1 = (const float*)d_in[2];
    const float* gw2 = (const float*)d_in[3];
    const float* gb2 = (const float*)d_in[4];
    const float* w1  = (const float*)d_in[5];
    const float* b1  = (const float*)d_in[6];
    const float* g1  = (const float*)d_in[7];
    const float* be1 = (const float*)d_in[8];
    const float* w2  = (const float*)d_in[9];
    const float* b2  = (const float*)d_in[10];
    const float* g2  = (const float*)d_in[11];
    const float* be2 = (const float*)d_in[12];
    const float* w3  = (const float*)d_in[13];
    const float* b3  = (const float*)d_in[14];
    float* out = (float*)d_out;

    cudaFuncSetAttribute(gating_kernel,
        cudaFuncAttributeMaxDynamicSharedMemorySize, GATE_SMEM);
    cudaFuncSetAttribute(expert_kernel,
        cudaFuncAttributeMaxDynamicSharedMemorySize, EXP_SMEM);

    zero_cnt_kernel<<<1, 32>>>();
    prep_x_kernel<<<(B_TOK * 256 / 4) / 256, 256>>>(x);
    prep_w_kernel<<<dim3(16, 25), 256>>>(w1, w2, w3, gw1);
    gating_kernel<<<B_TOK / 128, 256, GATE_SMEM>>>(gb1, gw2, gb2);
    expert_kernel<<<dim3(B_TOK / 128, E_NUM), 256, EXP_SMEM>>>(
        b1, g1, be1, b2, g2, be2, b3);
    combine_kernel<<<(B_TOK * 256 / 4) / 256, 256>>>(out);
}

// round 5
// speedup vs baseline: 3.3488x; 1.2382x over previous
#include <cuda_runtime.h>
#include <cuda_fp16.h>
#include <cstdint>

#define B_TOK 32768
#define E_NUM 8

// ---------------------------------------------------------------------------
// Device globals
// ---------------------------------------------------------------------------
__device__ int   g_cnt[E_NUM];
__device__ int   g_ridx[E_NUM * B_TOK];   // token | (k<<15)
__device__ float g_rwt [E_NUM * B_TOK];
__device__ __half g_xhi[B_TOK * 256];
__device__ __half g_xlo[B_TOK * 256];
// 25 slots: 0..23 = layer*8+expert, 24 = gating gw1. Tiled fragment layout:
// per slot: [k16(16)][n8(32)] frags of 256B (two 8x8 b16 matrices per 128B)
__device__ __half g_wthi[25 * 65536];
__device__ __half g_wtlo[25 * 65536];
__device__ float g_scr[2 * B_TOK * 256];

// ---------------------------------------------------------------------------
// Helpers
// ---------------------------------------------------------------------------
__device__ __forceinline__ uint32_t smem_u32(const void* p) {
    uint32_t a;
    asm("{ .reg .u64 t; cvta.to.shared.u64 t, %1; cvt.u32.u64 %0, t; }" : "=r"(a) : "l"(p));
    return a;
}
__device__ __forceinline__ void cp_async16(uint32_t dst, const void* src) {
    asm volatile("cp.async.cg.shared.global [%0], [%1], 16;" :: "r"(dst), "l"(src));
}
__device__ __forceinline__ void cp_async16z(uint32_t dst, const void* src, int srcsz) {
    asm volatile("cp.async.cg.shared.global [%0], [%1], 16, %2;"
                 :: "r"(dst), "l"(src), "r"(srcsz));
}
#define CP_COMMIT() asm volatile("cp.async.commit_group;" ::: "memory")
#define CP_WAIT0()  asm volatile("cp.async.wait_group 0;" ::: "memory")

__device__ __forceinline__ void ldsm4(uint32_t* r, uint32_t addr) {
    asm volatile("ldmatrix.sync.aligned.m8n8.x4.shared.b16 {%0,%1,%2,%3}, [%4];"
                 : "=r"(r[0]), "=r"(r[1]), "=r"(r[2]), "=r"(r[3]) : "r"(addr));
}
__device__ __forceinline__ void mma16816(float* c, const uint32_t* a, const uint32_t* b) {
    asm volatile("mma.sync.aligned.m16n8k16.row.col.f32.f16.f16.f32 "
                 "{%0,%1,%2,%3}, {%4,%5,%6,%7}, {%8,%9}, {%0,%1,%2,%3};"
                 : "+f"(c[0]), "+f"(c[1]), "+f"(c[2]), "+f"(c[3])
                 : "r"(a[0]), "r"(a[1]), "r"(a[2]), "r"(a[3]), "r"(b[0]), "r"(b[1]));
}
__device__ __forceinline__ uint32_t packh2(float a, float b) {
    __half2 h = __floats2half2_rn(a, b);
    return *(uint32_t*)&h;
}

// ---------------------------------------------------------------------------
// Shared memory layouts
// ---------------------------------------------------------------------------
// Gating (3-term): A hi/lo frags 2*65536, W dbuf 2*32768 at 131072
#define A_VAR_STRIDE 65536
#define GT_W_OFF  131072
#define WBUF_BYTES 32768
#define GT_GW2  196608
#define GT_GB1  204800
#define GT_LGS  205888
#define GT_GB2  209984
#define GT_SCNT 210048
#define GT_SBASE 210080
#define GT_SOFF 210112
#define GATE_SMEM 212992

// Expert (2-term, A hi only): A 0..65536, W dbuf 65536..131072
#define EX_W_OFF 65536
#define EX_STAT  131072
#define EX_SBV   133120
#define EX_SGV   134144
#define EX_SEV   135168
#define EX_SIDX  136192
#define EX_SGW   136704
#define EXP_SMEM 137216

// A fragment byte offset for element (row m, k)
__device__ __forceinline__ uint32_t a_frag_off(int m, int k) {
    return (uint32_t)((((k >> 4) * 8 + (m >> 4)) * 512) +
                      ((((k >> 3) & 1) * 2 + ((m >> 3) & 1)) * 128) +
                      ((m & 7) * 16) + ((k & 7) * 2));
}

// copy one 32KB W chunk (hi 16KB + lo 16KB, k-extent 32) into a smem buffer
__device__ __forceinline__ void copy_wchunk(uint32_t dst, const __half* wth,
                                            const __half* wtl, int c, int tid) {
    const char* sh = (const char*)wth + c * 16384;
    const char* sl = (const char*)wtl + c * 16384;
#pragma unroll
    for (int u = 0; u < 4; u++) {
        int o = (tid + u * 256) * 16;
        cp_async16(dst + o, sh + o);
    }
#pragma unroll
    for (int u = 0; u < 4; u++) {
        int o = (tid + u * 256) * 16;
        cp_async16(dst + 16384 + o, sl + o);
    }
}

// ---------------------------------------------------------------------------
// Gating mainloop (3-term split). One barrier per chunk; prefetch after sync.
// NOTE: no trailing sync — caller must sync before touching smem.
// ---------------------------------------------------------------------------
__device__ __forceinline__ void mma_mainloop3(
    uint32_t sa, const __half* wth, const __half* wtl,
    float (&acc)[2][16][4], int wm, int wn, int lane, int tid)
{
#pragma unroll
    for (int a = 0; a < 2; a++)
#pragma unroll
        for (int b = 0; b < 16; b++)
#pragma unroll
            for (int c = 0; c < 4; c++) acc[a][b][c] = 0.f;

    uint32_t aW = sa + GT_W_OFF;
    copy_wchunk(aW, wth, wtl, 0, tid);
    CP_COMMIT();

#pragma unroll 1
    for (int c = 0; c < 8; c++) {
        CP_WAIT0();
        __syncthreads();
        if (c < 7) {
            copy_wchunk(aW + ((c + 1) & 1) * WBUF_BYTES, wth, wtl, c + 1, tid);
            CP_COMMIT();
        }
        uint32_t wb = aW + (c & 1) * WBUF_BYTES;
#pragma unroll
        for (int ks = 0; ks < 2; ks++) {
            int k16 = c * 2 + ks;
            uint32_t ah[2][4], al[2][4];
#pragma unroll
            for (int mf = 0; mf < 2; mf++) {
                uint32_t base = sa + (uint32_t)((k16 * 8 + wm * 2 + mf) * 512) + lane * 16;
                ldsm4(ah[mf], base);
                ldsm4(al[mf], base + A_VAR_STRIDE);
            }
            uint32_t wb2 = wb + (uint32_t)((ks * 32 + wn * 16) * 256) + lane * 16;
            uint32_t b0[4], b1[4];
            ldsm4(b0, wb2);                       // j=0 hi
#pragma unroll
            for (int j = 0; j < 8; j++) {
                ldsm4(b1, wb2 + j * 512 + 16384); // j lo
#pragma unroll
                for (int mf = 0; mf < 2; mf++) {
                    mma16816(acc[mf][j * 2],     ah[mf], b0);
                    mma16816(acc[mf][j * 2 + 1], ah[mf], b0 + 2);
                    mma16816(acc[mf][j * 2],     al[mf], b0);
                    mma16816(acc[mf][j * 2 + 1], al[mf], b0 + 2);
                }
                uint32_t bl0 = b1[0], bl1 = b1[1], bl2 = b1[2], bl3 = b1[3];
                if (j < 7) ldsm4(b0, wb2 + (j + 1) * 512);  // next hi in flight
                uint32_t bl[4] = {bl0, bl1, bl2, bl3};
#pragma unroll
                for (int mf = 0; mf < 2; mf++) {
                    mma16816(acc[mf][j * 2],     ah[mf], bl);
                    mma16816(acc[mf][j * 2 + 1], ah[mf], bl + 2);
                }
            }
        }
    }
}

// ---------------------------------------------------------------------------
// Expert mainloop (2-term: Ahi*Whi + Ahi*Wlo). A hi frags at sa+0.
// ---------------------------------------------------------------------------
__device__ __forceinline__ void mma_mainloop2(
    uint32_t sa, const __half* wth, const __half* wtl,
    float (&acc)[2][16][4], int wm, int wn, int lane, int tid)
{
#pragma unroll
    for (int a = 0; a < 2; a++)
#pragma unroll
        for (int b = 0; b < 16; b++)
#pragma unroll
            for (int c = 0; c < 4; c++) acc[a][b][c] = 0.f;

    uint32_t aW = sa + EX_W_OFF;
    copy_wchunk(aW, wth, wtl, 0, tid);
    CP_COMMIT();

#pragma unroll 1
    for (int c = 0; c < 8; c++) {
        CP_WAIT0();
        __syncthreads();
        if (c < 7) {
            copy_wchunk(aW + ((c + 1) & 1) * WBUF_BYTES, wth, wtl, c + 1, tid);
            CP_COMMIT();
        }
        uint32_t wb = aW + (c & 1) * WBUF_BYTES;
#pragma unroll
        for (int ks = 0; ks < 2; ks++) {
            int k16 = c * 2 + ks;
            uint32_t ah[2][4];
#pragma unroll
            for (int mf = 0; mf < 2; mf++)
                ldsm4(ah[mf], sa + (uint32_t)((k16 * 8 + wm * 2 + mf) * 512) + lane * 16);
            uint32_t wb2 = wb + (uint32_t)((ks * 32 + wn * 16) * 256) + lane * 16;
            uint32_t b0[4], b1[4];
            ldsm4(b0, wb2);                       // j=0 hi
#pragma unroll
            for (int j = 0; j < 8; j++) {
                ldsm4(b1, wb2 + j * 512 + 16384); // j lo
#pragma unroll
                for (int mf = 0; mf < 2; mf++) {
                    mma16816(acc[mf][j * 2],     ah[mf], b0);
                    mma16816(acc[mf][j * 2 + 1], ah[mf], b0 + 2);
                }
                uint32_t bl0 = b1[0], bl1 = b1[1], bl2 = b1[2], bl3 = b1[3];
                if (j < 7) ldsm4(b0, wb2 + (j + 1) * 512);
                uint32_t bl[4] = {bl0, bl1, bl2, bl3};
#pragma unroll
                for (int mf = 0; mf < 2; mf++) {
                    mma16816(acc[mf][j * 2],     ah[mf], bl);
                    mma16816(acc[mf][j * 2 + 1], ah[mf], bl + 2);
                }
            }
        }
    }
}

// ---------------------------------------------------------------------------
// Prep kernels
// ---------------------------------------------------------------------------
__global__ void prep_x_kernel(const float* __restrict__ x) {
    if (blockIdx.x == 0 && threadIdx.x < E_NUM) g_cnt[threadIdx.x] = 0;
    int i = blockIdx.x * 256 + threadIdx.x;
    float4 v = ((const float4*)x)[i];
    __half h0 = __float2half_rn(v.x), h1 = __float2half_rn(v.y);
    __half h2 = __float2half_rn(v.z), h3 = __float2half_rn(v.w);
    uint2 hp, lp;
    hp.x = (uint32_t)__half_as_ushort(h0) | ((uint32_t)__half_as_ushort(h1) << 16);
    hp.y = (uint32_t)__half_as_ushort(h2) | ((uint32_t)__half_as_ushort(h3) << 16);
    __half l0 = __float2half_rn(v.x - __half2float(h0));
    __half l1 = __float2half_rn(v.y - __half2float(h1));
    __half l2 = __float2half_rn(v.z - __half2float(h2));
    __half l3 = __float2half_rn(v.w - __half2float(h3));
    lp.x = (uint32_t)__half_as_ushort(l0) | ((uint32_t)__half_as_ushort(l1) << 16);
    lp.y = (uint32_t)__half_as_ushort(l2) | ((uint32_t)__half_as_ushort(l3) << 16);
    ((uint2*)g_xhi)[i] = hp;
    ((uint2*)g_xlo)[i] = lp;
}

// One block per (k16, slot): read 16x256 fp32, emit tiled fp16 hi/lo frags.
__global__ void prep_w_kernel(const float* __restrict__ w1, const float* __restrict__ w2,
                              const float* __restrict__ w3, const float* __restrict__ gw1) {
    __shared__ float sm[16 * 256];
    int k16 = blockIdx.x, slot = blockIdx.y;
    const float* src;
    if (slot < 24) {
        int l = slot >> 3, e = slot & 7;
        src = ((l == 0) ? w1 : (l == 1) ? w2 : w3) + (size_t)e * 65536;
    } else {
        src = gw1;
    }
    src += (size_t)k16 * 16 * 256;
    int tid = threadIdx.x;
#pragma unroll
    for (int u = 0; u < 4; u++)
        ((float4*)sm)[tid + u * 256] = ((const float4*)src)[tid + u * 256];
    __syncthreads();

#pragma unroll
    for (int u = 0; u < 4; u++) {
        int id = tid + u * 256;
        int var = id >> 9;
        int rem = id & 511;
        int n8 = rem >> 4, sub = rem & 15;
        int kpart = sub >> 3, nrow = sub & 7;
        int n = n8 * 8 + nrow;
        ushort h[8];
#pragma unroll
        for (int i = 0; i < 8; i++) {
            float v = sm[(kpart * 8 + i) * 256 + n];
            __half hi = __float2half_rn(v);
            if (var == 0) h[i] = __half_as_ushort(hi);
            else          h[i] = __half_as_ushort(__float2half_rn(v - __half2float(hi)));
        }
        __half* dstbase = (var == 0) ? g_wthi : g_wtlo;
        uint4* dst = (uint4*)(dstbase + (size_t)slot * 65536 +
                              (k16 * 32 + n8) * 128 + kpart * 64 + nrow * 8);
        uint4 pk;
        pk.x = (uint32_t)h[0] | ((uint32_t)h[1] << 16);
        pk.y = (uint32_t)h[2] | ((uint32_t)h[3] << 16);
        pk.z = (uint32_t)h[4] | ((uint32_t)h[5] << 16);
        pk.w = (uint32_t)h[6] | ((uint32_t)h[7] << 16);
        *dst = pk;
    }
}

// ---------------------------------------------------------------------------
// Gating kernel: 128 tokens/CTA, 3-term mma layer1 + fp32 layer2 + top-2
// ---------------------------------------------------------------------------
__global__ __launch_bounds__(256, 1) void gating_kernel(
    const float* __restrict__ gb1,
    const float* __restrict__ gw2, const float* __restrict__ gb2)
{
    extern __shared__ char smraw[];
    uint32_t sa = smem_u32(smraw);
    float* hsm  = (float*)smraw;                    // after GEMM: h fp32 [128][260]
    float* gw2s = (float*)(smraw + GT_GW2);
    float* gb1s = (float*)(smraw + GT_GB1);
    float* lgs  = (float*)(smraw + GT_LGS);
    float* gb2s = (float*)(smraw + GT_GB2);
    int* scnt  = (int*)(smraw + GT_SCNT);
    int* sbase = (int*)(smraw + GT_SBASE);
    int* soff  = (int*)(smraw + GT_SOFF);

    int tid = threadIdx.x;
    int lane = tid & 31, warp = tid >> 5;
    int wm = warp & 3, wn = warp >> 2;

#pragma unroll
    for (int u = 0; u < 8; u++) gw2s[tid + u * 256] = gw2[tid + u * 256];
    gb1s[tid] = gb1[tid];
    if (tid < 8) { gb2s[tid] = gb2[tid]; scnt[tid] = 0; soff[tid] = 0; }

    // gather x tile into A hi/lo frags
    int rowbase = blockIdx.x * 128;
#pragma unroll
    for (int u = 0; u < 32; u++) {
        int id = tid + u * 256;
        int var = id >> 12;
        int rem = id & 4095;
        int row = rem >> 5, k8 = rem & 31;
        const __half* src = ((var == 0) ? g_xhi : g_xlo) +
                            (size_t)(rowbase + row) * 256 + k8 * 8;
        cp_async16(sa + var * A_VAR_STRIDE + a_frag_off(row, k8 * 8), src);
    }
    CP_COMMIT();

    float acc[2][16][4];
    mma_mainloop3(sa, g_wthi + 24 * 65536, g_wtlo + 24 * 65536, acc, wm, wn, lane, tid);
    __syncthreads();   // all warps done reading A/W before hsm overwrite

    // epilogue: h = relu(acc + gb1) -> hsm fp32 pitch 260
    int q = lane & 3, lr = lane >> 2;
#pragma unroll
    for (int mf = 0; mf < 2; mf++)
#pragma unroll
        for (int h = 0; h < 2; h++) {
            int row = wm * 32 + mf * 16 + h * 8 + lr;
#pragma unroll
            for (int nf = 0; nf < 16; nf++) {
                int col = wn * 128 + nf * 8 + q * 2;
                float2 o;
                o.x = fmaxf(acc[mf][nf][2 * h]     + gb1s[col],     0.f);
                o.y = fmaxf(acc[mf][nf][2 * h + 1] + gb1s[col + 1], 0.f);
                *(float2*)(hsm + row * 260 + col) = o;
            }
        }
    __syncthreads();

    // layer 2: logits[128][8]
    {
        int t = tid >> 1, eb = (tid & 1) * 4;
        const float* hr = hsm + t * 260;
        float s0 = gb2s[eb], s1 = gb2s[eb + 1], s2 = gb2s[eb + 2], s3 = gb2s[eb + 3];
#pragma unroll 4
        for (int k = 0; k < 256; k++) {
            float hv = hr[k];
            const float* g = gw2s + k * 8 + eb;
            s0 = fmaf(hv, g[0], s0);
            s1 = fmaf(hv, g[1], s1);
            s2 = fmaf(hv, g[2], s2);
            s3 = fmaf(hv, g[3], s3);
        }
        float* lp = lgs + t * 8 + eb;
        lp[0] = s0; lp[1] = s1; lp[2] = s2; lp[3] = s3;
    }
    __syncthreads();

    // top-2 + routing
    int i0 = 0, i1 = 0;
    float w0f = 0.f, w1f = 0.f;
    int token = rowbase + tid;
    if (tid < 128) {
        float l0 = -1e30f, l1 = -1e30f;
#pragma unroll
        for (int e = 0; e < E_NUM; e++) {
            float l = lgs[tid * 8 + e];
            if (l > l0) { l1 = l0; i1 = i0; l0 = l; i0 = e; }
            else if (l > l1) { l1 = l; i1 = e; }
        }
        float r = expf(l1 - l0);
        w0f = 1.f / (1.f + r);
        w1f = r * w0f;
        atomicAdd(&scnt[i0], 1);
        atomicAdd(&scnt[i1], 1);
    }
    __syncthreads();
    if (tid < E_NUM) sbase[tid] = atomicAdd(&g_cnt[tid], scnt[tid]);
    __syncthreads();
    if (tid < 128) {
        int p0 = atomicAdd(&soff[i0], 1);
        g_ridx[i0 * B_TOK + sbase[i0] + p0] = token;
        g_rwt [i0 * B_TOK + sbase[i0] + p0] = w0f;
        int p1 = atomicAdd(&soff[i1], 1);
        g_ridx[i1 * B_TOK + sbase[i1] + p1] = token | 32768;
        g_rwt [i1 * B_TOK + sbase[i1] + p1] = w1f;
    }
}

// ---------------------------------------------------------------------------
// Expert kernel (2-term split, A hi only)
// ---------------------------------------------------------------------------
__global__ __launch_bounds__(256, 1) void expert_kernel(
    const float* __restrict__ b1, const float* __restrict__ g1, const float* __restrict__ be1,
    const float* __restrict__ b2, const float* __restrict__ g2, const float* __restrict__ be2,
    const float* __restrict__ b3)
{
    int e = blockIdx.y;
    int n = g_cnt[e];
    int start = blockIdx.x * 128;
    if (start >= n) return;

    extern __shared__ char smraw[];
    uint32_t sa = smem_u32(smraw);
    float* sstat = (float*)(smraw + EX_STAT);
    float* sbv = (float*)(smraw + EX_SBV);
    float* sgv = (float*)(smraw + EX_SGV);
    float* sev = (float*)(smraw + EX_SEV);
    int*   sidx = (int*)(smraw + EX_SIDX);
    float* sgwv = (float*)(smraw + EX_SGW);

    int tid = threadIdx.x;
    int lane = tid & 31, warp = tid >> 5;
    int wm = warp & 3, wn = warp >> 2;

    if (tid < 128) {
        int r = start + tid;
        if (r < n) { sidx[tid] = g_ridx[e * B_TOK + r]; sgwv[tid] = g_rwt[e * B_TOK + r]; }
        else       { sidx[tid] = -1; sgwv[tid] = 0.f; }
    }
    __syncthreads();

    // gather routed x rows (hi only) into A frags
#pragma unroll
    for (int u = 0; u < 16; u++) {
        int id = tid + u * 256;
        int row = id >> 5, k8 = id & 31;
        int idx = sidx[row];
        int tok = idx & 32767;
        cp_async16z(sa + a_frag_off(row, k8 * 8),
                    g_xhi + (size_t)tok * 256 + k8 * 8, (idx >= 0) ? 16 : 0);
    }
    CP_COMMIT();

    const float* Bp[3] = {b1 + e * 256, b2 + e * 256, b3 + e * 256};
    const float* Gp[2] = {g1 + e * 256, g2 + e * 256};
    const float* Ep[2] = {be1 + e * 256, be2 + e * 256};

    float acc[2][16][4];
    int q = lane & 3, lr = lane >> 2;

#pragma unroll 1
    for (int layer = 0; layer < 3; layer++) {
        sbv[tid] = Bp[layer][tid];
        if (layer < 2) { sgv[tid] = Gp[layer][tid]; sev[tid] = Ep[layer][tid]; }
        int slot = layer * 8 + e;
        mma_mainloop2(sa, g_wthi + (size_t)slot * 65536, g_wtlo + (size_t)slot * 65536,
                      acc, wm, wn, lane, tid);

        if (layer < 2) {
            // bias + partial stats (regs + sstat only — no A/W hazard yet)
#pragma unroll
            for (int mf = 0; mf < 2; mf++)
#pragma unroll
                for (int h = 0; h < 2; h++) {
                    int row = wm * 32 + mf * 16 + h * 8 + lr;
                    float s = 0.f, s2 = 0.f;
#pragma unroll
                    for (int nf = 0; nf < 16; nf++) {
                        int col = wn * 128 + nf * 8 + q * 2;
                        float v0 = acc[mf][nf][2 * h]     + sbv[col];
                        float v1 = acc[mf][nf][2 * h + 1] + sbv[col + 1];
                        acc[mf][nf][2 * h] = v0;
                        acc[mf][nf][2 * h + 1] = v1;
                        s += v0 + v1;
                        s2 = fmaf(v0, v0, fmaf(v1, v1, s2));
                    }
                    s  += __shfl_xor_sync(0xffffffffu, s, 1);
                    s2 += __shfl_xor_sync(0xffffffffu, s2, 1);
                    s  += __shfl_xor_sync(0xffffffffu, s, 2);
                    s2 += __shfl_xor_sync(0xffffffffu, s2, 2);
                    if (q == 0) {
                        sstat[(row * 2 + wn) * 2]     = s;
                        sstat[(row * 2 + wn) * 2 + 1] = s2;
                    }
                }
            __syncthreads();   // stats visible AND all warps done with A/W reads
            // normalize + relu + re-split (hi only) into A frags
#pragma unroll
            for (int mf = 0; mf < 2; mf++)
#pragma unroll
                for (int h = 0; h < 2; h++) {
                    int row = wm * 32 + mf * 16 + h * 8 + lr;
                    float s  = sstat[row * 4]     + sstat[row * 4 + 2];
                    float s2 = sstat[row * 4 + 1] + sstat[row * 4 + 3];
                    float m = s * (1.f / 256.f);
                    float rstd = rsqrtf(s2 * (1.f / 256.f) - m * m + 1e-5f);
#pragma unroll
                    for (int nf = 0; nf < 16; nf++) {
                        int col = wn * 128 + nf * 8 + q * 2;
                        float v0 = fmaxf((acc[mf][nf][2 * h] - m) * rstd * sgv[col] + sev[col], 0.f);
                        float v1 = fmaxf((acc[mf][nf][2 * h + 1] - m) * rstd * sgv[col + 1] + sev[col + 1], 0.f);
                        uint32_t hi = packh2(v0, v1);
                        asm volatile("st.shared.b32 [%0], %1;"
                                     :: "r"(sa + a_frag_off(row, col)), "r"(hi));
                    }
                }
            __syncthreads();   // A writes visible before next mainloop / sbv rewrite
        } else {
            // output epilogue: (acc + b3) * gate -> scratch slot
#pragma unroll
            for (int mf = 0; mf < 2; mf++)
#pragma unroll
                for (int h = 0; h < 2; h++) {
                    int row = wm * 32 + mf * 16 + h * 8 + lr;
                    int idx = sidx[row];
                    if (idx < 0) continue;
                    float g = sgwv[row];
                    float* dst = g_scr + (size_t)(idx >> 15) * B_TOK * 256 +
                                 (size_t)(idx & 32767) * 256;
#pragma unroll
                    for (int nf = 0; nf < 16; nf++) {
                        int col = wn * 128 + nf * 8 + q * 2;
                        float2 o;
                        o.x = (acc[mf][nf][2 * h]     + sbv[col])     * g;
                        o.y = (acc[mf][nf][2 * h + 1] + sbv[col + 1]) * g;
                        *(float2*)(dst + col) = o;
                    }
                }
        }
    }
}

// ---------------------------------------------------------------------------
// Combine the two top-k slots
// ---------------------------------------------------------------------------
__global__ void combine_kernel(float* __restrict__ out) {
    int i = blockIdx.x * 256 + threadIdx.x;
    float4 a = ((const float4*)g_scr)[i];
    float4 b = ((const float4*)(g_scr + (size_t)B_TOK * 256))[i];
    float4 o;
    o.x = a.x + b.x; o.y = a.y + b.y; o.z = a.z + b.z; o.w = a.w + b.w;
    ((float4*)out)[i] = o;
}

// ---------------------------------------------------------------------------
// Launch
// ---------------------------------------------------------------------------
extern "C" void kernel_launch(void* const* d_in, const int* in_sizes, int n_in,
                              void* d_out, int out_size)
{
    (void)in_sizes; (void)n_in; (void)out_size;
    const float* x   = (const float*)d_in[0];
    const float* gw1 = (const float*)d_in[1];
    const float* gb1 = (const float*)d_in[2];
    const float* gw2 = (const float*)d_in[3];
    const float* gb2 = (const float*)d_in[4];
    const float* w1  = (const float*)d_in[5];
    const float* b1  = (const float*)d_in[6];
    const float* g1  = (const float*)d_in[7];
    const float* be1 = (const float*)d_in[8];
    const float* w2  = (const float*)d_in[9];
    const float* b2  = (const float*)d_in[10];
    const float* g2  = (const float*)d_in[11];
    const float* be2 = (const float*)d_in[12];
    const float* w3  = (const float*)d_in[13];
    const float* b3  = (const float*)d_in[14];
    float* out = (float*)d_out;

    cudaFuncSetAttribute(gating_kernel,
        cudaFuncAttributeMaxDynamicSharedMemorySize, GATE_SMEM);
    cudaFuncSetAttribute(expert_kernel,
        cudaFuncAttributeMaxDynamicSharedMemorySize, EXP_SMEM);

    prep_x_kernel<<<(B_TOK * 256 / 4) / 256, 256>>>(x);
    prep_w_kernel<<<dim3(16, 25), 256>>>(w1, w2, w3, gw1);
    gating_kernel<<<B_TOK / 128, 256, GATE_SMEM>>>(gb1, gw2, gb2);
    expert_kernel<<<dim3(B_TOK / 128, E_NUM), 256, EXP_SMEM>>>(
        b1, g1, be1, b2, g2, be2, b3);
    combine_kernel<<<(B_TOK * 256 / 4) / 256, 256>>>(out);
}

// round 6
// speedup vs baseline: 3.3996x; 1.0152x over previous
#include <cuda_runtime.h>
#include <cuda_fp16.h>
#include <cstdint>

#define B_TOK 32768
#define E_NUM 8

// ---------------------------------------------------------------------------
// Device globals
// ---------------------------------------------------------------------------
__device__ int   g_cnt[E_NUM];
__device__ int   g_ridx[E_NUM * B_TOK];   // token | (k<<15)
__device__ float g_rwt [E_NUM * B_TOK];
__device__ __half g_xhi[B_TOK * 256];
__device__ __half g_xlo[B_TOK * 256];
// 25 slots: 0..23 = layer*8+expert, 24 = gating gw1. Tiled fragment layout:
// per slot: [k16(16)][n8(32)] frags of 256B (two 8x8 b16 matrices per 128B)
__device__ __half g_wthi[25 * 65536];
__device__ __half g_wtlo[25 * 65536];
__device__ float g_scr[2 * B_TOK * 256];

// ---------------------------------------------------------------------------
// Helpers
// ---------------------------------------------------------------------------
__device__ __forceinline__ uint32_t smem_u32(const void* p) {
    uint32_t a;
    asm("{ .reg .u64 t; cvta.to.shared.u64 t, %1; cvt.u32.u64 %0, t; }" : "=r"(a) : "l"(p));
    return a;
}
__device__ __forceinline__ void cp_async16(uint32_t dst, const void* src) {
    asm volatile("cp.async.cg.shared.global [%0], [%1], 16;" :: "r"(dst), "l"(src));
}
__device__ __forceinline__ void cp_async16z(uint32_t dst, const void* src, int srcsz) {
    asm volatile("cp.async.cg.shared.global [%0], [%1], 16, %2;"
                 :: "r"(dst), "l"(src), "r"(srcsz));
}
#define CP_COMMIT() asm volatile("cp.async.commit_group;" ::: "memory")
#define CP_WAIT0()  asm volatile("cp.async.wait_group 0;" ::: "memory")

__device__ __forceinline__ void ldsm4(uint32_t* r, uint32_t addr) {
    asm volatile("ldmatrix.sync.aligned.m8n8.x4.shared.b16 {%0,%1,%2,%3}, [%4];"
                 : "=r"(r[0]), "=r"(r[1]), "=r"(r[2]), "=r"(r[3]) : "r"(addr));
}
__device__ __forceinline__ void mma16816(float* c, const uint32_t* a, const uint32_t* b) {
    asm volatile("mma.sync.aligned.m16n8k16.row.col.f32.f16.f16.f32 "
                 "{%0,%1,%2,%3}, {%4,%5,%6,%7}, {%8,%9}, {%0,%1,%2,%3};"
                 : "+f"(c[0]), "+f"(c[1]), "+f"(c[2]), "+f"(c[3])
                 : "r"(a[0]), "r"(a[1]), "r"(a[2]), "r"(a[3]), "r"(b[0]), "r"(b[1]));
}
__device__ __forceinline__ uint32_t packh2(float a, float b) {
    __half2 h = __floats2half2_rn(a, b);
    return *(uint32_t*)&h;
}

// ---------------------------------------------------------------------------
// Shared memory layouts
// ---------------------------------------------------------------------------
#define A_VAR_STRIDE 65536
#define WBUF_BYTES 32768
// Gating (3-term): A hi/lo 2*65536, W dbuf at 131072
#define GT_W_OFF  131072
#define GT_GW2  196608
#define GT_GB1  204800
#define GT_LGS  205888
#define GT_GB2  209984
#define GT_SCNT 210048
#define GT_SBASE 210080
#define GT_SOFF 210112
#define GATE_SMEM 212992
// Expert (2-term, A hi only)
#define EX_W_OFF 65536
#define EX_STAT  131072
#define EX_SBV   135168
#define EX_SGV   136192
#define EX_SEV   137216
#define EX_SIDX  138240
#define EX_SGW   138752
#define EXP_SMEM 139264

// A fragment byte offset for element (row m, k)
__device__ __forceinline__ uint32_t a_frag_off(int m, int k) {
    return (uint32_t)((((k >> 4) * 8 + (m >> 4)) * 512) +
                      ((((k >> 3) & 1) * 2 + ((m >> 3) & 1)) * 128) +
                      ((m & 7) * 16) + ((k & 7) * 2));
}

// copy one 32KB W chunk (hi 16KB + lo 16KB, k-extent 32), 512 threads
__device__ __forceinline__ void copy_wchunk(uint32_t dst, const __half* wth,
                                            const __half* wtl, int c, int tid) {
    const char* sh = (const char*)wth + c * 16384;
    const char* sl = (const char*)wtl + c * 16384;
#pragma unroll
    for (int u = 0; u < 2; u++) {
        int o = (tid + u * 512) * 16;
        cp_async16(dst + o, sh + o);
    }
#pragma unroll
    for (int u = 0; u < 2; u++) {
        int o = (tid + u * 512) * 16;
        cp_async16(dst + 16384 + o, sl + o);
    }
}

// ---------------------------------------------------------------------------
// Gating mainloop (3-term). 16 warps, warp tile 32x64. No trailing sync.
// ---------------------------------------------------------------------------
__device__ __forceinline__ void mma_mainloop3(
    uint32_t sa, const __half* wth, const __half* wtl,
    float (&acc)[2][8][4], int wm, int wn, int lane, int tid)
{
#pragma unroll
    for (int a = 0; a < 2; a++)
#pragma unroll
        for (int b = 0; b < 8; b++)
#pragma unroll
            for (int c = 0; c < 4; c++) acc[a][b][c] = 0.f;

    uint32_t aW = sa + GT_W_OFF;
    copy_wchunk(aW, wth, wtl, 0, tid);
    CP_COMMIT();

#pragma unroll 1
    for (int c = 0; c < 8; c++) {
        CP_WAIT0();
        __syncthreads();
        if (c < 7) {
            copy_wchunk(aW + ((c + 1) & 1) * WBUF_BYTES, wth, wtl, c + 1, tid);
            CP_COMMIT();
        }
        uint32_t wb = aW + (c & 1) * WBUF_BYTES;
#pragma unroll
        for (int ks = 0; ks < 2; ks++) {
            int k16 = c * 2 + ks;
            uint32_t ah[2][4], al[2][4];
#pragma unroll
            for (int mf = 0; mf < 2; mf++) {
                uint32_t base = sa + (uint32_t)((k16 * 8 + wm * 2 + mf) * 512) + lane * 16;
                ldsm4(ah[mf], base);
                ldsm4(al[mf], base + A_VAR_STRIDE);
            }
            uint32_t wb2 = wb + (uint32_t)((ks * 32 + wn * 8) * 256) + lane * 16;
            uint32_t b0[4], b1[4];
            ldsm4(b0, wb2);                       // j=0 hi
#pragma unroll
            for (int j = 0; j < 4; j++) {
                ldsm4(b1, wb2 + j * 512 + 16384); // j lo
#pragma unroll
                for (int mf = 0; mf < 2; mf++) {
                    mma16816(acc[mf][j * 2],     ah[mf], b0);
                    mma16816(acc[mf][j * 2 + 1], ah[mf], b0 + 2);
                    mma16816(acc[mf][j * 2],     al[mf], b0);
                    mma16816(acc[mf][j * 2 + 1], al[mf], b0 + 2);
                }
                uint32_t bl0 = b1[0], bl1 = b1[1], bl2 = b1[2], bl3 = b1[3];
                if (j < 3) ldsm4(b0, wb2 + (j + 1) * 512);  // next hi in flight
                uint32_t bl[4] = {bl0, bl1, bl2, bl3};
#pragma unroll
                for (int mf = 0; mf < 2; mf++) {
                    mma16816(acc[mf][j * 2],     ah[mf], bl);
                    mma16816(acc[mf][j * 2 + 1], ah[mf], bl + 2);
                }
            }
        }
    }
}

// ---------------------------------------------------------------------------
// Expert mainloop (2-term: Ahi*Whi + Ahi*Wlo). 16 warps, warp tile 32x64.
// ---------------------------------------------------------------------------
__device__ __forceinline__ void mma_mainloop2(
    uint32_t sa, const __half* wth, const __half* wtl,
    float (&acc)[2][8][4], int wm, int wn, int lane, int tid)
{
#pragma unroll
    for (int a = 0; a < 2; a++)
#pragma unroll
        for (int b = 0; b < 8; b++)
#pragma unroll
            for (int c = 0; c < 4; c++) acc[a][b][c] = 0.f;

    uint32_t aW = sa + EX_W_OFF;
    copy_wchunk(aW, wth, wtl, 0, tid);
    CP_COMMIT();

#pragma unroll 1
    for (int c = 0; c < 8; c++) {
        CP_WAIT0();
        __syncthreads();
        if (c < 7) {
            copy_wchunk(aW + ((c + 1) & 1) * WBUF_BYTES, wth, wtl, c + 1, tid);
            CP_COMMIT();
        }
        uint32_t wb = aW + (c & 1) * WBUF_BYTES;
#pragma unroll
        for (int ks = 0; ks < 2; ks++) {
            int k16 = c * 2 + ks;
            uint32_t ah[2][4];
#pragma unroll
            for (int mf = 0; mf < 2; mf++)
                ldsm4(ah[mf], sa + (uint32_t)((k16 * 8 + wm * 2 + mf) * 512) + lane * 16);
            uint32_t wb2 = wb + (uint32_t)((ks * 32 + wn * 8) * 256) + lane * 16;
            uint32_t b0[4], b1[4];
            ldsm4(b0, wb2);                       // j=0 hi
#pragma unroll
            for (int j = 0; j < 4; j++) {
                ldsm4(b1, wb2 + j * 512 + 16384); // j lo
#pragma unroll
                for (int mf = 0; mf < 2; mf++) {
                    mma16816(acc[mf][j * 2],     ah[mf], b0);
                    mma16816(acc[mf][j * 2 + 1], ah[mf], b0 + 2);
                }
                uint32_t bl0 = b1[0], bl1 = b1[1], bl2 = b1[2], bl3 = b1[3];
                if (j < 3) ldsm4(b0, wb2 + (j + 1) * 512);
                uint32_t bl[4] = {bl0, bl1, bl2, bl3};
#pragma unroll
                for (int mf = 0; mf < 2; mf++) {
                    mma16816(acc[mf][j * 2],     ah[mf], bl);
                    mma16816(acc[mf][j * 2 + 1], ah[mf], bl + 2);
                }
            }
        }
    }
}

// ---------------------------------------------------------------------------
// Prep kernels
// ---------------------------------------------------------------------------
__global__ void prep_x_kernel(const float* __restrict__ x) {
    if (blockIdx.x == 0 && threadIdx.x < E_NUM) g_cnt[threadIdx.x] = 0;
    int i = blockIdx.x * 256 + threadIdx.x;
    float4 v = ((const float4*)x)[i];
    __half h0 = __float2half_rn(v.x), h1 = __float2half_rn(v.y);
    __half h2 = __float2half_rn(v.z), h3 = __float2half_rn(v.w);
    uint2 hp, lp;
    hp.x = (uint32_t)__half_as_ushort(h0) | ((uint32_t)__half_as_ushort(h1) << 16);
    hp.y = (uint32_t)__half_as_ushort(h2) | ((uint32_t)__half_as_ushort(h3) << 16);
    __half l0 = __float2half_rn(v.x - __half2float(h0));
    __half l1 = __float2half_rn(v.y - __half2float(h1));
    __half l2 = __float2half_rn(v.z - __half2float(h2));
    __half l3 = __float2half_rn(v.w - __half2float(h3));
    lp.x = (uint32_t)__half_as_ushort(l0) | ((uint32_t)__half_as_ushort(l1) << 16);
    lp.y = (uint32_t)__half_as_ushort(l2) | ((uint32_t)__half_as_ushort(l3) << 16);
    ((uint2*)g_xhi)[i] = hp;
    ((uint2*)g_xlo)[i] = lp;
}

// One block per (k16, slot): read 16x256 fp32, emit tiled fp16 hi/lo frags.
__global__ void prep_w_kernel(const float* __restrict__ w1, const float* __restrict__ w2,
                              const float* __restrict__ w3, const float* __restrict__ gw1) {
    __shared__ float sm[16 * 256];
    int k16 = blockIdx.x, slot = blockIdx.y;
    const float* src;
    if (slot < 24) {
        int l = slot >> 3, e = slot & 7;
        src = ((l == 0) ? w1 : (l == 1) ? w2 : w3) + (size_t)e * 65536;
    } else {
        src = gw1;
    }
    src += (size_t)k16 * 16 * 256;
    int tid = threadIdx.x;
#pragma unroll
    for (int u = 0; u < 4; u++)
        ((float4*)sm)[tid + u * 256] = ((const float4*)src)[tid + u * 256];
    __syncthreads();

#pragma unroll
    for (int u = 0; u < 4; u++) {
        int id = tid + u * 256;
        int var = id >> 9;
        int rem = id & 511;
        int n8 = rem >> 4, sub = rem & 15;
        int kpart = sub >> 3, nrow = sub & 7;
        int n = n8 * 8 + nrow;
        ushort h[8];
#pragma unroll
        for (int i = 0; i < 8; i++) {
            float v = sm[(kpart * 8 + i) * 256 + n];
            __half hi = __float2half_rn(v);
            if (var == 0) h[i] = __half_as_ushort(hi);
            else          h[i] = __half_as_ushort(__float2half_rn(v - __half2float(hi)));
        }
        __half* dstbase = (var == 0) ? g_wthi : g_wtlo;
        uint4* dst = (uint4*)(dstbase + (size_t)slot * 65536 +
                              (k16 * 32 + n8) * 128 + kpart * 64 + nrow * 8);
        uint4 pk;
        pk.x = (uint32_t)h[0] | ((uint32_t)h[1] << 16);
        pk.y = (uint32_t)h[2] | ((uint32_t)h[3] << 16);
        pk.z = (uint32_t)h[4] | ((uint32_t)h[5] << 16);
        pk.w = (uint32_t)h[6] | ((uint32_t)h[7] << 16);
        *dst = pk;
    }
}

// ---------------------------------------------------------------------------
// Gating kernel: 128 tokens/CTA, 512 threads, 3-term mma + fp32 layer2 + top-2
// ---------------------------------------------------------------------------
__global__ __launch_bounds__(512, 1) void gating_kernel(
    const float* __restrict__ gb1,
    const float* __restrict__ gw2, const float* __restrict__ gb2)
{
    extern __shared__ char smraw[];
    uint32_t sa = smem_u32(smraw);
    float* hsm  = (float*)smraw;                    // after GEMM: h fp32 [128][260]
    float* gw2s = (float*)(smraw + GT_GW2);
    float* gb1s = (float*)(smraw + GT_GB1);
    float* lgs  = (float*)(smraw + GT_LGS);
    float* gb2s = (float*)(smraw + GT_GB2);
    int* scnt  = (int*)(smraw + GT_SCNT);
    int* sbase = (int*)(smraw + GT_SBASE);
    int* soff  = (int*)(smraw + GT_SOFF);

    int tid = threadIdx.x;
    int lane = tid & 31, warp = tid >> 5;
    int wm = warp & 3, wn = warp >> 2;     // wm 0..3, wn 0..3

#pragma unroll
    for (int u = 0; u < 4; u++) gw2s[tid + u * 512] = gw2[tid + u * 512];
    if (tid < 256) gb1s[tid] = gb1[tid];
    if (tid < 8) { gb2s[tid] = gb2[tid]; scnt[tid] = 0; soff[tid] = 0; }

    // gather x tile into A hi/lo frags
    int rowbase = blockIdx.x * 128;
#pragma unroll
    for (int u = 0; u < 16; u++) {
        int id = tid + u * 512;
        int var = id >> 12;
        int rem = id & 4095;
        int row = rem >> 5, k8 = rem & 31;
        const __half* src = ((var == 0) ? g_xhi : g_xlo) +
                            (size_t)(rowbase + row) * 256 + k8 * 8;
        cp_async16(sa + var * A_VAR_STRIDE + a_frag_off(row, k8 * 8), src);
    }
    CP_COMMIT();

    float acc[2][8][4];
    mma_mainloop3(sa, g_wthi + 24 * 65536, g_wtlo + 24 * 65536, acc, wm, wn, lane, tid);
    __syncthreads();   // all warps done reading A/W before hsm overwrite

    // epilogue: h = relu(acc + gb1) -> hsm fp32 pitch 260
    int q = lane & 3, lr = lane >> 2;
#pragma unroll
    for (int mf = 0; mf < 2; mf++)
#pragma unroll
        for (int h = 0; h < 2; h++) {
            int row = wm * 32 + mf * 16 + h * 8 + lr;
#pragma unroll
            for (int nf = 0; nf < 8; nf++) {
                int col = wn * 64 + nf * 8 + q * 2;
                float2 o;
                o.x = fmaxf(acc[mf][nf][2 * h]     + gb1s[col],     0.f);
                o.y = fmaxf(acc[mf][nf][2 * h + 1] + gb1s[col + 1], 0.f);
                *(float2*)(hsm + row * 260 + col) = o;
            }
        }
    __syncthreads();

    // layer 2: logits[128][8], thread -> (token, 2 experts)
    {
        int t = tid >> 2, eb = (tid & 3) * 2;
        const float* hr = hsm + t * 260;
        float s0 = gb2s[eb], s1 = gb2s[eb + 1];
#pragma unroll 4
        for (int k = 0; k < 256; k++) {
            float hv = hr[k];
            s0 = fmaf(hv, gw2s[k * 8 + eb],     s0);
            s1 = fmaf(hv, gw2s[k * 8 + eb + 1], s1);
        }
        lgs[t * 8 + eb] = s0;
        lgs[t * 8 + eb + 1] = s1;
    }
    __syncthreads();

    // top-2 + routing
    int i0 = 0, i1 = 0;
    float w0f = 0.f, w1f = 0.f;
    int token = rowbase + tid;
    if (tid < 128) {
        float l0 = -1e30f, l1 = -1e30f;
#pragma unroll
        for (int e = 0; e < E_NUM; e++) {
            float l = lgs[tid * 8 + e];
            if (l > l0) { l1 = l0; i1 = i0; l0 = l; i0 = e; }
            else if (l > l1) { l1 = l; i1 = e; }
        }
        float r = expf(l1 - l0);
        w0f = 1.f / (1.f + r);
        w1f = r * w0f;
        atomicAdd(&scnt[i0], 1);
        atomicAdd(&scnt[i1], 1);
    }
    __syncthreads();
    if (tid < E_NUM) sbase[tid] = atomicAdd(&g_cnt[tid], scnt[tid]);
    __syncthreads();
    if (tid < 128) {
        int p0 = atomicAdd(&soff[i0], 1);
        g_ridx[i0 * B_TOK + sbase[i0] + p0] = token;
        g_rwt [i0 * B_TOK + sbase[i0] + p0] = w0f;
        int p1 = atomicAdd(&soff[i1], 1);
        g_ridx[i1 * B_TOK + sbase[i1] + p1] = token | 32768;
        g_rwt [i1 * B_TOK + sbase[i1] + p1] = w1f;
    }
}

// ---------------------------------------------------------------------------
// Expert kernel (2-term split, A hi only), 512 threads
// ---------------------------------------------------------------------------
__global__ __launch_bounds__(512, 1) void expert_kernel(
    const float* __restrict__ b1, const float* __restrict__ g1, const float* __restrict__ be1,
    const float* __restrict__ b2, const float* __restrict__ g2, const float* __restrict__ be2,
    const float* __restrict__ b3)
{
    int e = blockIdx.y;
    int n = g_cnt[e];
    int start = blockIdx.x * 128;
    if (start >= n) return;

    extern __shared__ char smraw[];
    uint32_t sa = smem_u32(smraw);
    float* sstat = (float*)(smraw + EX_STAT);
    float* sbv = (float*)(smraw + EX_SBV);
    float* sgv = (float*)(smraw + EX_SGV);
    float* sev = (float*)(smraw + EX_SEV);
    int*   sidx = (int*)(smraw + EX_SIDX);
    float* sgwv = (float*)(smraw + EX_SGW);

    int tid = threadIdx.x;
    int lane = tid & 31, warp = tid >> 5;
    int wm = warp & 3, wn = warp >> 2;     // wm 0..3, wn 0..3

    if (tid < 128) {
        int r = start + tid;
        if (r < n) { sidx[tid] = g_ridx[e * B_TOK + r]; sgwv[tid] = g_rwt[e * B_TOK + r]; }
        else       { sidx[tid] = -1; sgwv[tid] = 0.f; }
    }
    __syncthreads();

    // gather routed x rows (hi only) into A frags
#pragma unroll
    for (int u = 0; u < 8; u++) {
        int id = tid + u * 512;
        int row = id >> 5, k8 = id & 31;
        int idx = sidx[row];
        int tok = idx & 32767;
        cp_async16z(sa + a_frag_off(row, k8 * 8),
                    g_xhi + (size_t)tok * 256 + k8 * 8, (idx >= 0) ? 16 : 0);
    }
    CP_COMMIT();

    const float* Bp[3] = {b1 + e * 256, b2 + e * 256, b3 + e * 256};
    const float* Gp[2] = {g1 + e * 256, g2 + e * 256};
    const float* Ep[2] = {be1 + e * 256, be2 + e * 256};

    float acc[2][8][4];
    int q = lane & 3, lr = lane >> 2;

#pragma unroll 1
    for (int layer = 0; layer < 3; layer++) {
        if (tid < 256) {
            sbv[tid] = Bp[layer][tid];
            if (layer < 2) { sgv[tid] = Gp[layer][tid]; sev[tid] = Ep[layer][tid]; }
        }
        int slot = layer * 8 + e;
        mma_mainloop2(sa, g_wthi + (size_t)slot * 65536, g_wtlo + (size_t)slot * 65536,
                      acc, wm, wn, lane, tid);

        if (layer < 2) {
            // bias + partial stats (regs + sstat only — no A/W hazard yet)
#pragma unroll
            for (int mf = 0; mf < 2; mf++)
#pragma unroll
                for (int h = 0; h < 2; h++) {
                    int row = wm * 32 + mf * 16 + h * 8 + lr;
                    float s = 0.f, s2 = 0.f;
#pragma unroll
                    for (int nf = 0; nf < 8; nf++) {
                        int col = wn * 64 + nf * 8 + q * 2;
                        float v0 = acc[mf][nf][2 * h]     + sbv[col];
                        float v1 = acc[mf][nf][2 * h + 1] + sbv[col + 1];
                        acc[mf][nf][2 * h] = v0;
                        acc[mf][nf][2 * h + 1] = v1;
                        s += v0 + v1;
                        s2 = fmaf(v0, v0, fmaf(v1, v1, s2));
                    }
                    s  += __shfl_xor_sync(0xffffffffu, s, 1);
                    s2 += __shfl_xor_sync(0xffffffffu, s2, 1);
                    s  += __shfl_xor_sync(0xffffffffu, s, 2);
                    s2 += __shfl_xor_sync(0xffffffffu, s2, 2);
                    if (q == 0) {
                        sstat[row * 8 + wn * 2]     = s;
                        sstat[row * 8 + wn * 2 + 1] = s2;
                    }
                }
            __syncthreads();   // stats visible AND all warps done with A/W reads
            // normalize + relu + re-split (hi only) into A frags
#pragma unroll
            for (int mf = 0; mf < 2; mf++)
#pragma unroll
                for (int h = 0; h < 2; h++) {
                    int row = wm * 32 + mf * 16 + h * 8 + lr;
                    float s  = sstat[row * 8]     + sstat[row * 8 + 2] +
                               sstat[row * 8 + 4] + sstat[row * 8 + 6];
                    float s2 = sstat[row * 8 + 1] + sstat[row * 8 + 3] +
                               sstat[row * 8 + 5] + sstat[row * 8 + 7];
                    float m = s * (1.f / 256.f);
                    float rstd = rsqrtf(s2 * (1.f / 256.f) - m * m + 1e-5f);
#pragma unroll
                    for (int nf = 0; nf < 8; nf++) {
                        int col = wn * 64 + nf * 8 + q * 2;
                        float v0 = fmaxf((acc[mf][nf][2 * h] - m) * rstd * sgv[col] + sev[col], 0.f);
                        float v1 = fmaxf((acc[mf][nf][2 * h + 1] - m) * rstd * sgv[col + 1] + sev[col + 1], 0.f);
                        uint32_t hi = packh2(v0, v1);
                        asm volatile("st.shared.b32 [%0], %1;"
                                     :: "r"(sa + a_frag_off(row, col)), "r"(hi));
                    }
                }
            __syncthreads();   // A writes visible before next mainloop / sbv rewrite
        } else {
            // output epilogue: (acc + b3) * gate -> scratch slot
#pragma unroll
            for (int mf = 0; mf < 2; mf++)
#pragma unroll
                for (int h = 0; h < 2; h++) {
                    int row = wm * 32 + mf * 16 + h * 8 + lr;
                    int idx = sidx[row];
                    if (idx < 0) continue;
                    float g = sgwv[row];
                    float* dst = g_scr + (size_t)(idx >> 15) * B_TOK * 256 +
                                 (size_t)(idx & 32767) * 256;
#pragma unroll
                    for (int nf = 0; nf < 8; nf++) {
                        int col = wn * 64 + nf * 8 + q * 2;
                        float2 o;
                        o.x = (acc[mf][nf][2 * h]     + sbv[col])     * g;
                        o.y = (acc[mf][nf][2 * h + 1] + sbv[col + 1]) * g;
                        *(float2*)(dst + col) = o;
                    }
                }
        }
    }
}

// ---------------------------------------------------------------------------
// Combine the two top-k slots
// ---------------------------------------------------------------------------
__global__ void combine_kernel(float* __restrict__ out) {
    int i = blockIdx.x * 256 + threadIdx.x;
    float4 a = ((const float4*)g_scr)[i];
    float4 b = ((const float4*)(g_scr + (size_t)B_TOK * 256))[i];
    float4 o;
    o.x = a.x + b.x; o.y = a.y + b.y; o.z = a.z + b.z; o.w = a.w + b.w;
    ((float4*)out)[i] = o;
}

// ---------------------------------------------------------------------------
// Launch
// ---------------------------------------------------------------------------
extern "C" void kernel_launch(void* const* d_in, const int* in_sizes, int n_in,
                              void* d_out, int out_size)
{
    (void)in_sizes; (void)n_in; (void)out_size;
    const float* x   = (const float*)d_in[0];
    const float* gw1 = (const float*)d_in[1];
    const float* gb1 = (const float*)d_in[2];
    const float* gw2 = (const float*)d_in[3];
    const float* gb2 = (const float*)d_in[4];
    const float* w1  = (const float*)d_in[5];
    const float* b1  = (const float*)d_in[6];
    const float* g1  = (const float*)d_in[7];
    const float* be1 = (const float*)d_in[8];
    const float* w2  = (const float*)d_in[9];
    const float* b2  = (const float*)d_in[10];
    const float* g2  = (const float*)d_in[11];
    const float* be2 = (const float*)d_in[12];
    const float* w3  = (const float*)d_in[13];
    const float* b3  = (const float*)d_in[14];
    float* out = (float*)d_out;

    cudaFuncSetAttribute(gating_kernel,
        cudaFuncAttributeMaxDynamicSharedMemorySize, GATE_SMEM);
    cudaFuncSetAttribute(expert_kernel,
        cudaFuncAttributeMaxDynamicSharedMemorySize, EXP_SMEM);

    prep_x_kernel<<<(B_TOK * 256 / 4) / 256, 256>>>(x);
    prep_w_kernel<<<dim3(16, 25), 256>>>(w1, w2, w3, gw1);
    gating_kernel<<<B_TOK / 128, 512, GATE_SMEM>>>(gb1, gw2, gb2);
    expert_kernel<<<dim3(B_TOK / 128, E_NUM), 512, EXP_SMEM>>>(
        b1, g1, be1, b2, g2, be2, b3);
    combine_kernel<<<(B_TOK * 256 / 4) / 256, 256>>>(out);
}